// round 10
// baseline (speedup 1.0000x reference)
#include <cuda_runtime.h>
#include <math.h>

// Fixed problem shapes:
// feat0 [2,256,200,200] f32, feat1 [2,256,100,100], feat2 [2,256,50,50],
// feat3 [2,256,25,25], boxes [2,256,4] f32 -> out [512,256,7,7] f32.
#define KROIS   512
#define NC      256
#define OUTHW   7
#define NBINS   49
#define WARPS   8               // warps per block
#define CPW     4               // channels per warp (2 pair-iterations)
#define CPB     (WARPS * CPW)   // 32 channels per block
#define GRPS    (NC / CPB)      // 8 channel-groups per roi
#define TSTRIDE 28              // 7*28 floats = 49 aligned float4 per channel

__device__ __forceinline__ void prep_coord(float c, int size,
                                           int& lo, int& hi, float& l, float& h)
{
    c = fmaxf(c, 0.0f);
    lo = (int)c;
    if (lo >= size - 1) { lo = size - 1; hi = size - 1; }
    else                { hi = lo + 1; }
    l = c - (float)lo;
    h = 1.0f - l;
}

// Predicated global load: when doload==0 the LDG is predicated off for the
// whole warp -> no L1 wavefront, no memory access. Returns 0 in that case.
__device__ __forceinline__ float ldg_pred(const float* ptr, int doload)
{
    float r = 0.0f;
    asm("{\n\t"
        ".reg .pred p;\n\t"
        "setp.ne.s32 p, %1, 0;\n\t"
        "@p ld.global.nc.f32 %0, [%2];\n\t"
        "}" : "+f"(r) : "r"(doload), "l"(ptr));
    return r;
}

__global__ void __launch_bounds__(256, 5)
roi_align_dedup_kernel(const float* __restrict__ f0,
                       const float* __restrict__ f1,
                       const float* __restrict__ f2,
                       const float* __restrict__ f3,
                       const float* __restrict__ boxes,
                       float* __restrict__ out)
{
    __shared__ float  s_temp[WARPS][2][OUTHW * TSTRIDE];  // 12.25 KB
    __shared__ int4   s_yoff[OUTHW];
    __shared__ float4 s_yw[OUTHW];
    __shared__ float  s_f[4];
    __shared__ int    s_i[2];

    const int k   = blockIdx.x >> 3;          // roi  (GRPS = 8)
    const int grp = blockIdx.x & (GRPS - 1);
    const int tid = threadIdx.x;

    // ---- per-roi scalars (thread 0 only) ----
    if (tid == 0) {
        const float4 bx = __ldg((const float4*)boxes + k);
        float x1 = bx.x, y1 = bx.y, x2 = bx.z, y2 = bx.w;

        float area = (x2 - x1) * (y2 - y1);
        float s    = sqrtf(area);
        float lvl  = floorf(4.0f + log2f(s / 224.0f) + 1e-6f);
        lvl = fminf(fmaxf(lvl, 2.0f), 5.0f);
        int level = (int)lvl - 2;

        const float scales[4] = {0.25f, 0.125f, 0.0625f, 0.03125f};
        const int   dims[4]   = {200, 100, 50, 25};
        float sc = scales[level];
        int   W  = dims[level];

        float x1s = x1 * sc, y1s = y1 * sc;
        float x2s = x2 * sc, y2s = y2 * sc;

        s_f[0] = x1s;
        s_f[1] = y1s;
        s_f[2] = fmaxf(x2s - x1s, 1.0f) / (float)OUTHW;
        s_f[3] = fmaxf(y2s - y1s, 1.0f) / (float)OUTHW;
        s_i[0] = level;
        s_i[1] = W;
    }
    __syncthreads();

    const int   level = s_i[0];
    const int   W     = s_i[1];
    const float x1s   = s_f[0];
    const float y1s   = s_f[1];
    const float bin_w = s_f[2];
    const float bin_h = s_f[3];

    // ---- y tables (threads 0-6) ----
    if (tid < OUTHW) {
        int p = tid;
        float half = bin_h * 0.5f;
        int lo0, hi0, lo1, hi1; float l0, h0, l1, h1;
        prep_coord(y1s + (float)p * bin_h + 0.5f * half, W, lo0, hi0, l0, h0);
        prep_coord(y1s + (float)p * bin_h + 1.5f * half, W, lo1, hi1, l1, h1);
        s_yoff[p] = make_int4(lo0 * W, hi0 * W, lo1 * W, hi1 * W);
        s_yw[p]   = make_float4(h0, l0, h1, l1);
    }
    __syncthreads();

    const int warp = tid >> 5;
    const int lane = tid & 31;
    const int c0   = grp * CPB + warp * CPW;
    const int b    = k >> 8;

    // ---- per-lane x corner: j = 4*pw + 2*ix + corner (lanes 28-31 mirror 27) ----
    const int j      = (lane < 28) ? lane : 27;
    const int si     = j >> 1;
    const int corner = j & 1;
    const int pwj    = si >> 1;
    const int ixj    = si & 1;

    float half_bw = bin_w * 0.5f;
    int xlo, xhi; float xl, xh;
    prep_coord(x1s + (float)pwj * bin_w + ((float)ixj + 0.5f) * half_bw, W,
               xlo, xhi, xl, xh);
    const int   xc = corner ? xhi : xlo;
    const float xw = 0.25f * (corner ? xl : xh);

    const float* feat;
    switch (level) {
        case 0:  feat = f0; break;
        case 1:  feat = f1; break;
        case 2:  feat = f2; break;
        default: feat = f3; break;
    }
    const int plane = W * W;
    const float* __restrict__ pb =
        feat + (size_t)((b * NC + c0) * W) * (size_t)W + xc;

    const float4* __restrict__ t40 = (const float4*)s_temp[warp][0];
    const float4* __restrict__ t41 = (const float4*)s_temp[warp][1];
    size_t obase = (size_t)(k * NC + c0) * NBINS;

    #pragma unroll 1
    for (int pp = 0; pp < CPW / 2; pp++) {
        // ---- phase A: per channel, dedup'd predicated loads then FMA+store ----
        #pragma unroll
        for (int ch = 0; ch < 2; ch++) {
            const float* __restrict__ p = pb + ch * plane;
            float v[OUTHW][4];
            int pz = -1, pw_ = -1;     // previous ph's lo1/hi1 row offsets
            #pragma unroll
            for (int ph = 0; ph < OUTHW; ph++) {
                int4 ro = s_yoff[ph];
                float pv2 = (ph > 0) ? v[ph - 1][2] : 0.0f;
                float pv3 = (ph > 0) ? v[ph - 1][3] : 0.0f;

                // x = lo0 : reuse prev hi1 / prev lo1
                int rx1 = (ro.x == pw_), rx2 = (ro.x == pz);
                float lx = ldg_pred(p + ro.x, !(rx1 | rx2));
                float v0 = rx1 ? pv3 : (rx2 ? pv2 : lx);

                // y = hi0 : reuse lo0 (clamp) / prev hi1
                int ry1 = (ro.y == ro.x), ry2 = (ro.y == pw_);
                float ly = ldg_pred(p + ro.y, !(ry1 | ry2));
                float v1 = ry1 ? v0 : (ry2 ? pv3 : ly);

                // z = lo1 : reuse hi0 / lo0
                int rz1 = (ro.z == ro.y), rz2 = (ro.z == ro.x);
                float lz = ldg_pred(p + ro.z, !(rz1 | rz2));
                float v2 = rz1 ? v1 : (rz2 ? v0 : lz);

                // w = hi1 : reuse lo1 (clamp) / hi0
                int rw1 = (ro.w == ro.z), rw2 = (ro.w == ro.y);
                float lw = ldg_pred(p + ro.w, !(rw1 | rw2));
                float v3 = rw1 ? v2 : (rw2 ? v1 : lw);

                v[ph][0] = v0; v[ph][1] = v1; v[ph][2] = v2; v[ph][3] = v3;
                pz = ro.z; pw_ = ro.w;
            }

            float* __restrict__ tw = s_temp[warp][ch];
            #pragma unroll
            for (int ph = 0; ph < OUTHW; ph++) {
                float4 yw = s_yw[ph];
                float a = yw.x * v[ph][0] + yw.y * v[ph][1]
                        + yw.z * v[ph][2] + yw.w * v[ph][3];
                if (lane < 28) tw[ph * TSTRIDE + j] = a * xw;
            }
        }
        __syncwarp();

        // ---- phase B: one LDS.128 per bin, 98 contiguous stores per warp ----
        #pragma unroll
        for (int o = lane; o < 2 * NBINS; o += 32) {
            float4 t = (o < NBINS) ? t40[o] : t41[o - NBINS];
            out[obase + o] = (t.x + t.y) + (t.z + t.w);
        }
        __syncwarp();

        pb    += 2 * plane;
        obase += 2 * NBINS;
    }
}

extern "C" void kernel_launch(void* const* d_in, const int* in_sizes, int n_in,
                              void* d_out, int out_size)
{
    const float* f0    = (const float*)d_in[0];
    const float* f1    = (const float*)d_in[1];
    const float* f2    = (const float*)d_in[2];
    const float* f3    = (const float*)d_in[3];
    const float* boxes = (const float*)d_in[4];
    float* out = (float*)d_out;

    const int blocks = KROIS * GRPS;   // 512 * 8 = 4096
    roi_align_dedup_kernel<<<blocks, 256>>>(f0, f1, f2, f3, boxes, out);
}

// round 11
// speedup vs baseline: 1.9161x; 1.9161x over previous
#include <cuda_runtime.h>
#include <math.h>

// Fixed problem shapes:
// feat0 [2,256,200,200] f32, feat1 [2,256,100,100], feat2 [2,256,50,50],
// feat3 [2,256,25,25], boxes [2,256,4] f32 -> out [512,256,7,7] f32.
#define KROIS   512
#define NC      256
#define OUTHW   7
#define NBINS   49
#define WARPS   8               // warps per block
#define CPW     4               // channels per warp (2 pair-iterations)
#define CPB     (WARPS * CPW)   // 32 channels per block
#define GRPS    (NC / CPB)      // 8 channel-groups per roi
#define TSTRIDE 28              // 7*28 floats = 49 aligned float4 per channel

__device__ __forceinline__ void prep_coord(float c, int size,
                                           int& lo, int& hi, float& l, float& h)
{
    c = fmaxf(c, 0.0f);
    lo = (int)c;
    if (lo >= size - 1) { lo = size - 1; hi = size - 1; }
    else                { hi = lo + 1; }
    l = c - (float)lo;
    h = 1.0f - l;
}

__global__ void __launch_bounds__(256, 7)
roi_align_4ch_hocc_kernel(const float* __restrict__ f0,
                          const float* __restrict__ f1,
                          const float* __restrict__ f2,
                          const float* __restrict__ f3,
                          const float* __restrict__ boxes,
                          float* __restrict__ out)
{
    __shared__ float  s_temp[WARPS][2][OUTHW * TSTRIDE];  // 12.25 KB
    __shared__ int4   s_yoff[OUTHW];
    __shared__ float4 s_yw[OUTHW];
    __shared__ float  s_f[4];
    __shared__ int    s_i[2];

    const int k   = blockIdx.x >> 3;          // roi  (GRPS = 8)
    const int grp = blockIdx.x & (GRPS - 1);
    const int tid = threadIdx.x;

    // ---- per-roi scalars (thread 0 only) ----
    if (tid == 0) {
        const float4 bx = __ldg((const float4*)boxes + k);
        float x1 = bx.x, y1 = bx.y, x2 = bx.z, y2 = bx.w;

        float area = (x2 - x1) * (y2 - y1);
        float s    = sqrtf(area);
        float lvl  = floorf(4.0f + log2f(s / 224.0f) + 1e-6f);
        lvl = fminf(fmaxf(lvl, 2.0f), 5.0f);
        int level = (int)lvl - 2;

        const float scales[4] = {0.25f, 0.125f, 0.0625f, 0.03125f};
        const int   dims[4]   = {200, 100, 50, 25};
        float sc = scales[level];
        int   W  = dims[level];

        float x1s = x1 * sc, y1s = y1 * sc;
        float x2s = x2 * sc, y2s = y2 * sc;

        s_f[0] = x1s;
        s_f[1] = y1s;
        s_f[2] = fmaxf(x2s - x1s, 1.0f) / (float)OUTHW;
        s_f[3] = fmaxf(y2s - y1s, 1.0f) / (float)OUTHW;
        s_i[0] = level;
        s_i[1] = W;
    }
    __syncthreads();

    const int   level = s_i[0];
    const int   W     = s_i[1];
    const float x1s   = s_f[0];
    const float y1s   = s_f[1];
    const float bin_w = s_f[2];
    const float bin_h = s_f[3];

    // ---- y tables (threads 0-6) ----
    if (tid < OUTHW) {
        int p = tid;
        float half = bin_h * 0.5f;
        int lo0, hi0, lo1, hi1; float l0, h0, l1, h1;
        prep_coord(y1s + (float)p * bin_h + 0.5f * half, W, lo0, hi0, l0, h0);
        prep_coord(y1s + (float)p * bin_h + 1.5f * half, W, lo1, hi1, l1, h1);
        s_yoff[p] = make_int4(lo0 * W, hi0 * W, lo1 * W, hi1 * W);
        s_yw[p]   = make_float4(h0, l0, h1, l1);
    }
    __syncthreads();

    const int warp = tid >> 5;
    const int lane = tid & 31;
    const int c0   = grp * CPB + warp * CPW;    // first of CPW adjacent channels
    const int b    = k >> 8;

    // ---- per-lane x corner: j = 4*pw + 2*ix + corner (lanes 28-31 mirror 27) ----
    const int j      = (lane < 28) ? lane : 27;
    const int si     = j >> 1;
    const int corner = j & 1;
    const int pwj    = si >> 1;
    const int ixj    = si & 1;

    float half_bw = bin_w * 0.5f;
    int xlo, xhi; float xl, xh;
    prep_coord(x1s + (float)pwj * bin_w + ((float)ixj + 0.5f) * half_bw, W,
               xlo, xhi, xl, xh);
    const int   xc = corner ? xhi : xlo;
    const float xw = 0.25f * (corner ? xl : xh);

    const float* feat;
    switch (level) {
        case 0:  feat = f0; break;
        case 1:  feat = f1; break;
        case 2:  feat = f2; break;
        default: feat = f3; break;
    }
    const int plane = W * W;
    const float* __restrict__ pb =
        feat + (size_t)((b * NC + c0) * W) * (size_t)W + xc;

    const float4* __restrict__ t40 = (const float4*)s_temp[warp][0];
    const float4* __restrict__ t41 = (const float4*)s_temp[warp][1];
    size_t obase = (size_t)(k * NC + c0) * NBINS;

    #pragma unroll 1
    for (int pp = 0; pp < CPW / 2; pp++) {
        // ---- phase A: per channel, batch 28 loads then FMA+store ----
        #pragma unroll
        for (int ch = 0; ch < 2; ch++) {
            const float* __restrict__ p = pb + ch * plane;
            float v[OUTHW][4];
            #pragma unroll
            for (int ph = 0; ph < OUTHW; ph++) {
                int4 ro = s_yoff[ph];
                v[ph][0] = __ldg(p + ro.x);
                v[ph][1] = __ldg(p + ro.y);
                v[ph][2] = __ldg(p + ro.z);
                v[ph][3] = __ldg(p + ro.w);
            }
            float* __restrict__ tw = s_temp[warp][ch];
            #pragma unroll
            for (int ph = 0; ph < OUTHW; ph++) {
                float4 yw = s_yw[ph];
                float a = yw.x * v[ph][0] + yw.y * v[ph][1]
                        + yw.z * v[ph][2] + yw.w * v[ph][3];
                if (lane < 28) tw[ph * TSTRIDE + j] = a * xw;
            }
        }
        __syncwarp();

        // ---- phase B: one LDS.128 per bin, 98 contiguous stores per warp ----
        #pragma unroll
        for (int o = lane; o < 2 * NBINS; o += 32) {
            float4 t = (o < NBINS) ? t40[o] : t41[o - NBINS];
            out[obase + o] = (t.x + t.y) + (t.z + t.w);
        }
        __syncwarp();

        pb    += 2 * plane;
        obase += 2 * NBINS;
    }
}

extern "C" void kernel_launch(void* const* d_in, const int* in_sizes, int n_in,
                              void* d_out, int out_size)
{
    const float* f0    = (const float*)d_in[0];
    const float* f1    = (const float*)d_in[1];
    const float* f2    = (const float*)d_in[2];
    const float* f3    = (const float*)d_in[3];
    const float* boxes = (const float*)d_in[4];
    float* out = (float*)d_out;

    const int blocks = KROIS * GRPS;   // 512 * 8 = 4096
    roi_align_4ch_hocc_kernel<<<blocks, 256>>>(f0, f1, f2, f3, boxes, out);
}

// round 12
// speedup vs baseline: 2.4738x; 1.2910x over previous
#include <cuda_runtime.h>
#include <math.h>

// Fixed problem shapes:
// feat0 [2,256,200,200] f32, feat1 [2,256,100,100], feat2 [2,256,50,50],
// feat3 [2,256,25,25], boxes [2,256,4] f32 -> out [512,256,7,7] f32.
#define KROIS   512
#define NC      256
#define OUTHW   7
#define NBINS   49
#define WARPS   8               // warps per block
#define CPW     4               // channels per warp (2 pair-iterations)
#define CPB     (WARPS * CPW)   // 32 channels per block
#define GRPS    (NC / CPB)      // 8 channel-groups per roi

__device__ __forceinline__ void prep_coord(float c, int size,
                                           int& lo, int& hi, float& l, float& h)
{
    c = fmaxf(c, 0.0f);
    lo = (int)c;
    if (lo >= size - 1) { lo = size - 1; hi = size - 1; }
    else                { hi = lo + 1; }
    l = c - (float)lo;
    h = 1.0f - l;
}

__global__ void __launch_bounds__(256, 6)
roi_align_bfly_kernel(const float* __restrict__ f0,
                      const float* __restrict__ f1,
                      const float* __restrict__ f2,
                      const float* __restrict__ f3,
                      const float* __restrict__ boxes,
                      float* __restrict__ out)
{
    __shared__ int4   s_yoff[OUTHW];
    __shared__ float4 s_yw[OUTHW];
    __shared__ float  s_f[4];
    __shared__ int    s_i[2];

    const int k   = blockIdx.x >> 3;          // roi  (GRPS = 8)
    const int grp = blockIdx.x & (GRPS - 1);
    const int tid = threadIdx.x;

    // ---- per-roi scalars (thread 0 only) ----
    if (tid == 0) {
        const float4 bx = __ldg((const float4*)boxes + k);
        float x1 = bx.x, y1 = bx.y, x2 = bx.z, y2 = bx.w;

        float area = (x2 - x1) * (y2 - y1);
        float s    = sqrtf(area);
        float lvl  = floorf(4.0f + log2f(s / 224.0f) + 1e-6f);
        lvl = fminf(fmaxf(lvl, 2.0f), 5.0f);
        int level = (int)lvl - 2;

        const float scales[4] = {0.25f, 0.125f, 0.0625f, 0.03125f};
        const int   dims[4]   = {200, 100, 50, 25};
        float sc = scales[level];
        int   W  = dims[level];

        float x1s = x1 * sc, y1s = y1 * sc;
        float x2s = x2 * sc, y2s = y2 * sc;

        s_f[0] = x1s;
        s_f[1] = y1s;
        s_f[2] = fmaxf(x2s - x1s, 1.0f) / (float)OUTHW;
        s_f[3] = fmaxf(y2s - y1s, 1.0f) / (float)OUTHW;
        s_i[0] = level;
        s_i[1] = W;
    }
    __syncthreads();

    const int   level = s_i[0];
    const int   W     = s_i[1];
    const float x1s   = s_f[0];
    const float y1s   = s_f[1];
    const float bin_w = s_f[2];
    const float bin_h = s_f[3];

    // ---- y tables (threads 0-6) ----
    if (tid < OUTHW) {
        int p = tid;
        float half = bin_h * 0.5f;
        int lo0, hi0, lo1, hi1; float l0, h0, l1, h1;
        prep_coord(y1s + (float)p * bin_h + 0.5f * half, W, lo0, hi0, l0, h0);
        prep_coord(y1s + (float)p * bin_h + 1.5f * half, W, lo1, hi1, l1, h1);
        s_yoff[p] = make_int4(lo0 * W, hi0 * W, lo1 * W, hi1 * W);
        s_yw[p]   = make_float4(h0, l0, h1, l1);
    }
    __syncthreads();

    const int warp = tid >> 5;
    const int lane = tid & 31;
    const int c0   = grp * CPB + warp * CPW;    // first of CPW adjacent channels
    const int b    = k >> 8;

    // ---- per-lane x corner: j = 4*pw + 2*ix + corner (lanes 28-31 mirror 27) ----
    const int j      = (lane < 28) ? lane : 27;
    const int si     = j >> 1;
    const int corner = j & 1;
    const int pwj    = si >> 1;
    const int ixj    = si & 1;

    float half_bw = bin_w * 0.5f;
    int xlo, xhi; float xl, xh;
    prep_coord(x1s + (float)pwj * bin_w + ((float)ixj + 0.5f) * half_bw, W,
               xlo, xhi, xl, xh);
    const int   xc = corner ? xhi : xlo;
    const float xw = 0.25f * (corner ? xl : xh);

    const float* feat;
    switch (level) {
        case 0:  feat = f0; break;
        case 1:  feat = f1; break;
        case 2:  feat = f2; break;
        default: feat = f3; break;
    }
    const int plane = W * W;
    const float* __restrict__ pb =
        feat + (size_t)((b * NC + c0) * W) * (size_t)W + xc;

    // store lane: lanes 0,4,...,24 write pw = lane>>2
    const bool wr  = (lane < 28) && ((lane & 3) == 0);
    const int  pwo = lane >> 2;
    size_t obase = (size_t)(k * NC + c0) * NBINS;

    #pragma unroll 1
    for (int pp = 0; pp < CPW / 2; pp++) {
        #pragma unroll
        for (int ch = 0; ch < 2; ch++) {
            const float* __restrict__ p = pb + ch * plane;

            // batch all 28 loads first (max MLP)
            float v[OUTHW][4];
            #pragma unroll
            for (int ph = 0; ph < OUTHW; ph++) {
                int4 ro = s_yoff[ph];
                v[ph][0] = __ldg(p + ro.x);
                v[ph][1] = __ldg(p + ro.y);
                v[ph][2] = __ldg(p + ro.z);
                v[ph][3] = __ldg(p + ro.w);
            }

            // y-FMA, x-weight, then 4-lane butterfly sum; direct store
            #pragma unroll
            for (int ph = 0; ph < OUTHW; ph++) {
                float4 yw = s_yw[ph];
                float a = (yw.x * v[ph][0] + yw.y * v[ph][1]
                         + yw.z * v[ph][2] + yw.w * v[ph][3]) * xw;
                a += __shfl_xor_sync(0xffffffffu, a, 1);
                a += __shfl_xor_sync(0xffffffffu, a, 2);
                if (wr) out[obase + ch * NBINS + ph * OUTHW + pwo] = a;
            }
        }
        pb    += 2 * plane;
        obase += 2 * NBINS;
    }
}

extern "C" void kernel_launch(void* const* d_in, const int* in_sizes, int n_in,
                              void* d_out, int out_size)
{
    const float* f0    = (const float*)d_in[0];
    const float* f1    = (const float*)d_in[1];
    const float* f2    = (const float*)d_in[2];
    const float* f3    = (const float*)d_in[3];
    const float* boxes = (const float*)d_in[4];
    float* out = (float*)d_out;

    const int blocks = KROIS * GRPS;   // 512 * 8 = 4096
    roi_align_bfly_kernel<<<blocks, 256>>>(f0, f1, f2, f3, boxes, out);
}